// round 8
// baseline (speedup 1.0000x reference)
#include <cuda_runtime.h>
#include <cuda_bf16.h>

// ForwardKinematics: B=524288, NA=7 joints, NJ=8 transforms.
// out[n] = M0*...*M6*F7, Mi = Fi*[[R(theta_i,a_i),0],[0,1]]
// rot(Mi) = A_i + sin*(A_i K_i) + (1-cos)*(A_i(aa^T) - A_i); trans(Mi)=t_i.
//
// R8: dur ~ inst/issue% across all rounds. Combine LOW REGS (scalar math,
// 1 elem/thread -> high occupancy) with TREE ILP (balanced product tree,
// depth 3 -> high per-warp issue). F7 folded into joint 6. Coalesced smem
// input stage. 64-reg cap via __launch_bounds__(256,4).

#define NACT 7
#define THREADS 256

struct Aff { float r[9]; float t[3]; };

// X = Y * Z (affine 3x4, implicit bottom row)
__device__ __forceinline__ void amul(const Aff& Y, const Aff& Z, Aff& X) {
    #pragma unroll
    for (int row = 0; row < 3; row++) {
        #pragma unroll
        for (int c = 0; c < 3; c++)
            X.r[row * 3 + c] = fmaf(Y.r[row * 3 + 2], Z.r[6 + c],
                               fmaf(Y.r[row * 3 + 1], Z.r[3 + c],
                                    Y.r[row * 3 + 0] * Z.r[c]));
        X.t[row] = fmaf(Y.r[row * 3 + 2], Z.t[2],
                   fmaf(Y.r[row * 3 + 1], Z.t[1],
                   fmaf(Y.r[row * 3 + 0], Z.t[0], Y.t[row])));
    }
}

__global__ __launch_bounds__(THREADS, 4)
void fk_kernel(const float* __restrict__ jp,    // (B,7)
               const float* __restrict__ ft,    // (8,4,4)
               const float* __restrict__ axes,  // (7,3)
               float* __restrict__ out,         // (B,4,4)
               int n)
{
    // per joint: A[12] B[12] C[12] (9 + pad, float4-packed), t/t6 block [12]
    __shared__ alignas(16) float s_in[THREADS * NACT];   // 1792 floats
    __shared__ alignas(16) float sA[NACT][12];
    __shared__ alignas(16) float sB[NACT][12];
    __shared__ alignas(16) float sC[NACT][12];
    __shared__ alignas(16) float sT[NACT][12];  // joints 0..5: t[3]; joint 6: at/bt/ct

    const int tid = threadIdx.x;

    if (tid < NACT) {
        const float* F = ft + tid * 16;
        float A[9], Bm[9], Cm[9];
        #pragma unroll
        for (int r = 0; r < 3; r++)
            #pragma unroll
            for (int c = 0; c < 3; c++)
                A[r * 3 + c] = F[r * 4 + c];
        const float ax = axes[tid * 3 + 0];
        const float ay = axes[tid * 3 + 1];
        const float az = axes[tid * 3 + 2];
        #pragma unroll
        for (int r = 0; r < 3; r++) {
            Bm[r * 3 + 0] = A[r * 3 + 1] * az - A[r * 3 + 2] * ay;
            Bm[r * 3 + 1] = A[r * 3 + 2] * ax - A[r * 3 + 0] * az;
            Bm[r * 3 + 2] = A[r * 3 + 0] * ay - A[r * 3 + 1] * ax;
        }
        #pragma unroll
        for (int r = 0; r < 3; r++) {
            float dp = A[r * 3 + 0] * ax + A[r * 3 + 1] * ay + A[r * 3 + 2] * az;
            Cm[r * 3 + 0] = dp * ax - A[r * 3 + 0];
            Cm[r * 3 + 1] = dp * ay - A[r * 3 + 1];
            Cm[r * 3 + 2] = dp * az - A[r * 3 + 2];
        }
        if (tid < 6) {
            #pragma unroll
            for (int k = 0; k < 9; k++) {
                sA[tid][k] = A[k]; sB[tid][k] = Bm[k]; sC[tid][k] = Cm[k];
            }
            #pragma unroll
            for (int k = 9; k < 12; k++) { sA[tid][k] = 0.f; sB[tid][k] = 0.f; sC[tid][k] = 0.f; }
            sT[tid][0] = F[3]; sT[tid][1] = F[7]; sT[tid][2] = F[11];
            #pragma unroll
            for (int k = 3; k < 12; k++) sT[tid][k] = 0.f;
        } else {
            // fold F7: rot' = rot*F7r  (A,B,C each right-multiplied by F7r)
            // trans' = (A f7t + t6) + s (B f7t) + o (C f7t)
            const float* F7 = ft + 7 * 16;
            float F7r[9], f7t[3];
            #pragma unroll
            for (int r = 0; r < 3; r++) {
                #pragma unroll
                for (int c = 0; c < 3; c++)
                    F7r[r * 3 + c] = F7[r * 4 + c];
                f7t[r] = F7[r * 4 + 3];
            }
            #pragma unroll
            for (int r = 0; r < 3; r++)
                #pragma unroll
                for (int c = 0; c < 3; c++) {
                    sA[6][r * 3 + c] = A[r * 3 + 0] * F7r[c] + A[r * 3 + 1] * F7r[3 + c] + A[r * 3 + 2] * F7r[6 + c];
                    sB[6][r * 3 + c] = Bm[r * 3 + 0] * F7r[c] + Bm[r * 3 + 1] * F7r[3 + c] + Bm[r * 3 + 2] * F7r[6 + c];
                    sC[6][r * 3 + c] = Cm[r * 3 + 0] * F7r[c] + Cm[r * 3 + 1] * F7r[3 + c] + Cm[r * 3 + 2] * F7r[6 + c];
                }
            #pragma unroll
            for (int k = 9; k < 12; k++) { sA[6][k] = 0.f; sB[6][k] = 0.f; sC[6][k] = 0.f; }
            #pragma unroll
            for (int r = 0; r < 3; r++) {
                sT[6][0 + r] = A[r * 3 + 0] * f7t[0] + A[r * 3 + 1] * f7t[1] + A[r * 3 + 2] * f7t[2] + F[r * 4 + 3];
                sT[6][4 + r] = Bm[r * 3 + 0] * f7t[0] + Bm[r * 3 + 1] * f7t[1] + Bm[r * 3 + 2] * f7t[2];
                sT[6][8 + r] = Cm[r * 3 + 0] * f7t[0] + Cm[r * 3 + 1] * f7t[1] + Cm[r * 3 + 2] * f7t[2];
            }
            sT[6][3] = sT[6][7] = sT[6][11] = 0.f;
        }
    }

    // ---- coalesced input stage: 448 float4 ----
    {
        const long long base_f = (long long)blockIdx.x * (THREADS * NACT);
        const long long total_f = (long long)n * NACT;
        #pragma unroll
        for (int j = 0; j < 2; j++) {
            int f4 = j * THREADS + tid;
            if (f4 < (THREADS * NACT) / 4) {
                long long g = base_f + (long long)f4 * 4;
                float4 v;
                if (g + 3 < total_f) v = *reinterpret_cast<const float4*>(jp + g);
                else {
                    v.x = (g + 0 < total_f) ? jp[g + 0] : 0.0f;
                    v.y = (g + 1 < total_f) ? jp[g + 1] : 0.0f;
                    v.z = (g + 2 < total_f) ? jp[g + 2] : 0.0f;
                    v.w = (g + 3 < total_f) ? jp[g + 3] : 0.0f;
                }
                *reinterpret_cast<float4*>(s_in + f4 * 4) = v;
            }
        }
    }
    __syncthreads();

    const int n_idx = blockIdx.x * THREADS + tid;
    if (n_idx >= n) return;

    const float* th = s_in + tid * NACT;   // stride 7: conflict-free

    // build Mi from smem constants (joints 0..5: plain t; joint 6: folded)
    auto buildM = [&](int i, Aff& M) {
        float s, c;
        __sincosf(th[i], &s, &c);
        const float o = 1.0f - c;
        const float4* Av = reinterpret_cast<const float4*>(sA[i]);
        const float4* Bv = reinterpret_cast<const float4*>(sB[i]);
        const float4* Cv = reinterpret_cast<const float4*>(sC[i]);
        #pragma unroll
        for (int q = 0; q < 3; q++) {
            float4 a = Av[q], b = Bv[q], cc = Cv[q];
            if (q * 4 + 0 < 9) M.r[q * 4 + 0] = fmaf(o, cc.x, fmaf(s, b.x, a.x));
            if (q * 4 + 1 < 9) M.r[q * 4 + 1] = fmaf(o, cc.y, fmaf(s, b.y, a.y));
            if (q * 4 + 2 < 9) M.r[q * 4 + 2] = fmaf(o, cc.z, fmaf(s, b.z, a.z));
            if (q * 4 + 3 < 9) M.r[q * 4 + 3] = fmaf(o, cc.w, fmaf(s, b.w, a.w));
        }
        if (i < 6) {
            float4 t0 = reinterpret_cast<const float4*>(sT[i])[0];
            M.t[0] = t0.x; M.t[1] = t0.y; M.t[2] = t0.z;
        } else {
            const float4* Tv = reinterpret_cast<const float4*>(sT[6]);
            float4 at = Tv[0], bt = Tv[1], ct = Tv[2];
            M.t[0] = fmaf(o, ct.x, fmaf(s, bt.x, at.x));
            M.t[1] = fmaf(o, ct.y, fmaf(s, bt.y, at.y));
            M.t[2] = fmaf(o, ct.z, fmaf(s, bt.z, at.z));
        }
    };

    Aff A, B, C, D;
    // Q0 = (M0*M1)*(M2*M3)
    buildM(0, A);
    buildM(1, B);
    amul(A, B, C);          // C = P0
    buildM(2, A);
    buildM(3, B);
    amul(A, B, D);          // D = P1
    amul(C, D, A);          // A = Q0
    // Q1 = (M4*M5)*M6'
    buildM(4, B);
    buildM(5, C);
    amul(B, C, D);          // D = P2
    buildM(6, B);           // B = M6' (F7 folded)
    amul(D, B, C);          // C = Q1
    // T = Q0*Q1
    amul(A, C, B);          // B = T

    float4* o = reinterpret_cast<float4*>(out + (size_t)n_idx * 16);
    o[0] = make_float4(B.r[0], B.r[1], B.r[2], B.t[0]);
    o[1] = make_float4(B.r[3], B.r[4], B.r[5], B.t[1]);
    o[2] = make_float4(B.r[6], B.r[7], B.r[8], B.t[2]);
    o[3] = make_float4(0.0f, 0.0f, 0.0f, 1.0f);
}

extern "C" void kernel_launch(void* const* d_in, const int* in_sizes, int n_in,
                              void* d_out, int out_size) {
    const float* jp   = (const float*)d_in[0];  // joint_positions (B,7)
    const float* ft   = (const float*)d_in[1];  // fixed_transforms (8,4,4)
    const float* axes = (const float*)d_in[2];  // joint_axes (7,3)
    float* out = (float*)d_out;
    const int n = in_sizes[0] / NACT;
    const int blocks = (n + THREADS - 1) / THREADS;
    fk_kernel<<<blocks, THREADS>>>(jp, ft, axes, out, n);
}

// round 9
// speedup vs baseline: 1.2145x; 1.2145x over previous
#include <cuda_runtime.h>
#include <cuda_bf16.h>

// ForwardKinematics: B=524288, NA=7 joints, NJ=8 transforms.
// out[n] = M0*...*M6*F7, Mi = Fi*[[R(theta_i,a_i),0],[0,1]]
// rot(Mi) = A_i + sin*(A_i K_i) + (1-cos)*(A_i(aa^T) - A_i); trans(Mi)=t_i.
//
// R9: move ALL per-joint constants to __constant__ memory (prep kernel ->
// cudaMemcpyToSymbolAsync D2D -> cbank). Blackwell reads these via LDC/LDCU
// on a separate port: zero LDS, zero smem, zero barriers in the hot kernel.
// Main kernel is otherwise the R1 scalar chain (44 regs, best occ/issue seen).
// F7 folded into joint 6.

#define NACT 7
#define THREADS 256

// constant layout: A[7][9] | B[7][9] | C[7][9] | t[6][3] | t6[9]
#define CA   0
#define CB   63
#define CC   126
#define CT   189
#define CT6  207
#define CST_SIZE 216

__constant__ float cst[CST_SIZE];
__device__ float g_prep[CST_SIZE];

__global__ void prep_kernel(const float* __restrict__ ft,
                            const float* __restrict__ axes)
{
    const int tid = threadIdx.x;
    if (tid >= NACT) return;

    const float* F = ft + tid * 16;
    float A[9], Bm[9], Cm[9];
    #pragma unroll
    for (int r = 0; r < 3; r++)
        #pragma unroll
        for (int c = 0; c < 3; c++)
            A[r * 3 + c] = F[r * 4 + c];
    const float ax = axes[tid * 3 + 0];
    const float ay = axes[tid * 3 + 1];
    const float az = axes[tid * 3 + 2];
    #pragma unroll
    for (int r = 0; r < 3; r++) {
        Bm[r * 3 + 0] = A[r * 3 + 1] * az - A[r * 3 + 2] * ay;
        Bm[r * 3 + 1] = A[r * 3 + 2] * ax - A[r * 3 + 0] * az;
        Bm[r * 3 + 2] = A[r * 3 + 0] * ay - A[r * 3 + 1] * ax;
    }
    #pragma unroll
    for (int r = 0; r < 3; r++) {
        float dp = A[r * 3 + 0] * ax + A[r * 3 + 1] * ay + A[r * 3 + 2] * az;
        Cm[r * 3 + 0] = dp * ax - A[r * 3 + 0];
        Cm[r * 3 + 1] = dp * ay - A[r * 3 + 1];
        Cm[r * 3 + 2] = dp * az - A[r * 3 + 2];
    }

    if (tid < 6) {
        #pragma unroll
        for (int k = 0; k < 9; k++) {
            g_prep[CA + tid * 9 + k] = A[k];
            g_prep[CB + tid * 9 + k] = Bm[k];
            g_prep[CC + tid * 9 + k] = Cm[k];
        }
        g_prep[CT + tid * 3 + 0] = F[3];
        g_prep[CT + tid * 3 + 1] = F[7];
        g_prep[CT + tid * 3 + 2] = F[11];
    } else {
        // joint 6 with F7 folded:
        // rot' = (A + sB + oC)*F7r  -> fold F7r into A,B,C
        // trans' = (A f7t + t6) + s (B f7t) + o (C f7t)
        const float* F7 = ft + 7 * 16;
        float F7r[9], f7t[3];
        #pragma unroll
        for (int r = 0; r < 3; r++) {
            #pragma unroll
            for (int c = 0; c < 3; c++)
                F7r[r * 3 + c] = F7[r * 4 + c];
            f7t[r] = F7[r * 4 + 3];
        }
        #pragma unroll
        for (int r = 0; r < 3; r++)
            #pragma unroll
            for (int c = 0; c < 3; c++) {
                g_prep[CA + 6 * 9 + r * 3 + c] =
                    A[r * 3 + 0] * F7r[c] + A[r * 3 + 1] * F7r[3 + c] + A[r * 3 + 2] * F7r[6 + c];
                g_prep[CB + 6 * 9 + r * 3 + c] =
                    Bm[r * 3 + 0] * F7r[c] + Bm[r * 3 + 1] * F7r[3 + c] + Bm[r * 3 + 2] * F7r[6 + c];
                g_prep[CC + 6 * 9 + r * 3 + c] =
                    Cm[r * 3 + 0] * F7r[c] + Cm[r * 3 + 1] * F7r[3 + c] + Cm[r * 3 + 2] * F7r[6 + c];
            }
        #pragma unroll
        for (int r = 0; r < 3; r++) {
            g_prep[CT6 + 0 + r] = A[r * 3 + 0] * f7t[0] + A[r * 3 + 1] * f7t[1] + A[r * 3 + 2] * f7t[2] + F[r * 4 + 3];
            g_prep[CT6 + 3 + r] = Bm[r * 3 + 0] * f7t[0] + Bm[r * 3 + 1] * f7t[1] + Bm[r * 3 + 2] * f7t[2];
            g_prep[CT6 + 6 + r] = Cm[r * 3 + 0] * f7t[0] + Cm[r * 3 + 1] * f7t[1] + Cm[r * 3 + 2] * f7t[2];
        }
    }
}

__global__ __launch_bounds__(THREADS)
void fk_kernel(const float* __restrict__ jp,    // (B,7)
               float* __restrict__ out,         // (B,4,4)
               int n)
{
    const int n_idx = blockIdx.x * THREADS + threadIdx.x;
    if (n_idx >= n) return;

    const float* p = jp + (size_t)n_idx * NACT;
    float th[NACT];
    #pragma unroll
    for (int i = 0; i < NACT; i++) th[i] = p[i];

    float Tr[9], Tt[3];

    // joint 0: T = M0
    {
        float s, c;
        __sincosf(th[0], &s, &c);
        const float o = 1.0f - c;
        #pragma unroll
        for (int k = 0; k < 9; k++)
            Tr[k] = fmaf(o, cst[CC + k], fmaf(s, cst[CB + k], cst[CA + k]));
        Tt[0] = cst[CT + 0]; Tt[1] = cst[CT + 1]; Tt[2] = cst[CT + 2];
    }

    // joints 1..5: T = T @ Mi
    #pragma unroll
    for (int i = 1; i < 6; i++) {
        float s, c;
        __sincosf(th[i], &s, &c);
        const float o = 1.0f - c;
        float M[9];
        #pragma unroll
        for (int k = 0; k < 9; k++)
            M[k] = fmaf(o, cst[CC + i * 9 + k], fmaf(s, cst[CB + i * 9 + k], cst[CA + i * 9 + k]));

        float R[9];
        #pragma unroll
        for (int r = 0; r < 3; r++)
            #pragma unroll
            for (int c2 = 0; c2 < 3; c2++)
                R[r * 3 + c2] = fmaf(Tr[r * 3 + 2], M[6 + c2],
                                fmaf(Tr[r * 3 + 1], M[3 + c2],
                                     Tr[r * 3 + 0] * M[0 + c2]));

        #pragma unroll
        for (int r = 0; r < 3; r++)
            Tt[r] = fmaf(Tr[r * 3 + 2], cst[CT + i * 3 + 2],
                    fmaf(Tr[r * 3 + 1], cst[CT + i * 3 + 1],
                    fmaf(Tr[r * 3 + 0], cst[CT + i * 3 + 0], Tt[r])));

        #pragma unroll
        for (int k = 0; k < 9; k++) Tr[k] = R[k];
    }

    // joint 6 (F7 folded): M6' rot from cst, trans = at + s*bt + o*ct
    float Rr[9], Ot[3];
    {
        float s, c;
        __sincosf(th[6], &s, &c);
        const float o = 1.0f - c;
        float M[9], Mt[3];
        #pragma unroll
        for (int k = 0; k < 9; k++)
            M[k] = fmaf(o, cst[CC + 6 * 9 + k], fmaf(s, cst[CB + 6 * 9 + k], cst[CA + 6 * 9 + k]));
        #pragma unroll
        for (int r = 0; r < 3; r++)
            Mt[r] = fmaf(o, cst[CT6 + 6 + r], fmaf(s, cst[CT6 + 3 + r], cst[CT6 + r]));

        #pragma unroll
        for (int r = 0; r < 3; r++) {
            #pragma unroll
            for (int c2 = 0; c2 < 3; c2++)
                Rr[r * 3 + c2] = fmaf(Tr[r * 3 + 2], M[6 + c2],
                                 fmaf(Tr[r * 3 + 1], M[3 + c2],
                                      Tr[r * 3 + 0] * M[0 + c2]));
            Ot[r] = fmaf(Tr[r * 3 + 2], Mt[2],
                    fmaf(Tr[r * 3 + 1], Mt[1],
                    fmaf(Tr[r * 3 + 0], Mt[0], Tt[r])));
        }
    }

    float4* o = reinterpret_cast<float4*>(out + (size_t)n_idx * 16);
    o[0] = make_float4(Rr[0], Rr[1], Rr[2], Ot[0]);
    o[1] = make_float4(Rr[3], Rr[4], Rr[5], Ot[1]);
    o[2] = make_float4(Rr[6], Rr[7], Rr[8], Ot[2]);
    o[3] = make_float4(0.0f, 0.0f, 0.0f, 1.0f);
}

extern "C" void kernel_launch(void* const* d_in, const int* in_sizes, int n_in,
                              void* d_out, int out_size) {
    const float* jp   = (const float*)d_in[0];  // joint_positions (B,7)
    const float* ft   = (const float*)d_in[1];  // fixed_transforms (8,4,4)
    const float* axes = (const float*)d_in[2];  // joint_axes (7,3)
    float* out = (float*)d_out;
    const int n = in_sizes[0] / NACT;

    prep_kernel<<<1, 32>>>(ft, axes);

    void* prep_ptr = nullptr;
    cudaGetSymbolAddress(&prep_ptr, g_prep);
    cudaMemcpyToSymbolAsync(cst, prep_ptr, CST_SIZE * sizeof(float), 0,
                            cudaMemcpyDeviceToDevice);

    const int blocks = (n + THREADS - 1) / THREADS;
    fk_kernel<<<blocks, THREADS>>>(jp, out, n);
}